// round 12
// baseline (speedup 1.0000x reference)
#include <cuda_runtime.h>
#include <math_constants.h>

#define NDIM  512
#define NKNOT 32
#define NDATA 65536
#define NBIN  (NKNOT + 1)     // 33: tail-low + 31 interior + tail-high

#define DT   32               // dims per block tile (one warp-width)
#define TPB  256              // 32 dims x 8 rows per iteration
#define BPT  55               // blocks per dim-tile (16*55=880 ~= 888 slots)
#define TAILW 64.0f           // tail fake-bin width (power of 2 -> exact xi)

// Bin coefficient records, bin-major, natural dim order: g_RA/g_RB[b*NDIM + d]
//   RA = {t0 = -x_lo/dx, inv_dx, a2, a1}   (P = a2 xi^2 + a1 xi + a0)
//   RB = {a0, c, s, e1 = 2(s - dl)}        (den = -c xi^2 + c xi + s,
//                                           num =  c xi^2 + e1 xi + dl)
__device__ float4 g_RA[NBIN * NDIM];
__device__ float4 g_RB[NBIN * NDIM];
__device__ float4 g_P2[4 * NDIM];            // {xx[8q+1], xx[8q+3], xx[8q+5], 0}
__device__ float  g_XE[(NKNOT / 2) * NDIM];  // xx[2j]
__device__ float4 g_P1[NDIM];                // {xx7, xx15, xx23, xx31}

// ---------------------------------------------------------------------------
// Prep: one warp per dim. Inclusive shfl-scan builds xx/yy; lane k holds
// knot k. Bin b (1..31) emitted by lane b from (prev-lane, own) knots.
// ---------------------------------------------------------------------------
__device__ __forceinline__ void emit_rec(int b, int d, float x_lo, float dx,
                                         float y_lo, float dy, float dl, float dh) {
    const float inv_dx = 1.0f / dx;
    const float s = dy * inv_dx;
    const float c = dh + dl - 2.0f * s;
    g_RA[b * NDIM + d] = make_float4(-x_lo * inv_dx, inv_dx,
                                     -y_lo * c + dy * (s - dl),
                                     y_lo * c + dy * dl);
    g_RB[b * NDIM + d] = make_float4(y_lo * s, c, s, 2.0f * (s - dl));
}

__global__ void prep_kernel(const float* __restrict__ params) {
    const unsigned FULL = 0xFFFFFFFFu;
    const int d    = (blockIdx.x * blockDim.x + threadIdx.x) >> 5;  // dim = warp
    const int lane = threadIdx.x & 31;
    if (d >= NDIM) return;

    float edx = 0.0f, edy = 0.0f;
    if (lane >= 1) {
        edx = expf(params[2 * NDIM + d * (NKNOT - 1) + lane - 1]);
        edy = expf(params[2 * NDIM + NDIM * (NKNOT - 1) + d * (NKNOT - 1) + lane - 1]);
    }
    const float dd = expf(params[2 * NDIM + 2 * NDIM * (NKNOT - 1) + d * NKNOT + lane]);

    #pragma unroll
    for (int o = 1; o < 32; o <<= 1) {
        const float tx = __shfl_up_sync(FULL, edx, o);
        const float ty = __shfl_up_sync(FULL, edy, o);
        if (lane >= o) { edx += tx; edy += ty; }
    }
    const float xx = params[d] + edx;         // lane k holds xx[k]
    const float yy = params[NDIM + d] + edy;  // lane k holds yy[k]

    const float xxp = __shfl_up_sync(FULL, xx, 1);
    const float yyp = __shfl_up_sync(FULL, yy, 1);
    const float ddp = __shfl_up_sync(FULL, dd, 1);

    if (lane == 0)
        emit_rec(0, d, xx - TAILW, TAILW, yy - TAILW * dd, TAILW * dd, dd, dd);
    else
        emit_rec(lane, d, xxp, xx - xxp, yyp, yy - yyp, ddp, dd);
    if (lane == NKNOT - 1)
        emit_rec(NKNOT, d, xx, TAILW, yy, TAILW * dd, dd, dd);

    // P2 pivots (lanes 0..3 write quadrant q = lane)
    const int q = lane & 3;
    const float x1 = __shfl_sync(FULL, xx, 8 * q + 1);
    const float x3 = __shfl_sync(FULL, xx, 8 * q + 3);
    const float x5 = __shfl_sync(FULL, xx, 8 * q + 5);
    if (lane < 4)
        g_P2[lane * NDIM + d] = make_float4(x1, x3, x5, 0.0f);

    // Even-knot table (lanes 0..15 write j = lane)
    const float xe = __shfl_sync(FULL, xx, 2 * (lane & 15));
    if (lane < 16)
        g_XE[lane * NDIM + d] = xe;

    // L1 pivots
    const float p7  = __shfl_sync(FULL, xx, 7);
    const float p15 = __shfl_sync(FULL, xx, 15);
    const float p23 = __shfl_sync(FULL, xx, 23);
    const float p31 = __shfl_sync(FULL, xx, 31);
    if (lane == 0)
        g_P1[d] = make_float4(p7, p15, p23, p31);
}

// ---------------------------------------------------------------------------
// Main kernel: persistent-style single wave (880 blocks ~= 888 resident
// slots). Each block fills its 32-dim tile tables ONCE, then strides its
// 8-row window across all NDATA rows (step BPT*8 = 440). Body identical to
// the proven R6 shape: tournament search + Horner RQ, conflict-free LDS.128.
// ---------------------------------------------------------------------------
__global__ __launch_bounds__(TPB, 6) void spline_kernel(
    const float* __restrict__ x, float* __restrict__ out)
{
    __shared__ float4 sRA[NBIN * DT];           // 16.5 KB
    __shared__ float4 sRB[NBIN * DT];           // 16.5 KB
    __shared__ float4 sP2[4 * DT];              // 2 KB
    __shared__ float  sXE[(NKNOT / 2) * DT];    // 2 KB

    const int dbase = blockIdx.x * DT;
    const int tid = threadIdx.x;

    #pragma unroll
    for (int i = tid; i < NBIN * DT; i += TPB) {
        int g = (i >> 5) * NDIM + dbase + (i & 31);
        sRA[i] = g_RA[g];
        sRB[i] = g_RB[g];
    }
    if (tid < 4 * DT)
        sP2[tid] = g_P2[(tid >> 5) * NDIM + dbase + (tid & 31)];
    #pragma unroll
    for (int i = tid; i < (NKNOT / 2) * DT; i += TPB)
        sXE[i] = g_XE[(i >> 5) * NDIM + dbase + (i & 31)];

    const int d  = tid & 31;
    const int rl = tid >> 5;                     // 0..7

    // Per-thread L1 pivots (hoisted; p1.w = xx[31]).
    const float4 p1 = g_P1[dbase + d];

    __syncthreads();

    float* __restrict__ yout  = out;
    float* __restrict__ ldout = out + NDATA * NDIM;

    const int r_init = blockIdx.y * (TPB / DT) + rl;     // 0..439
    const unsigned step = BPT * (TPB / DT) * NDIM;       // 440 rows

    unsigned off = (unsigned)r_init * NDIM + dbase + d;

    #pragma unroll 4
    for (int r = r_init; r < NDATA; r += BPT * (TPB / DT), off += step) {
        const float xv = __ldg(x + off);

        // --- tournament: b = #{knots < xv} in [0, 32] ---
        const int q = (p1.x < xv) + (p1.y < xv) + (p1.z < xv);
        const float4 p2 = sP2[q * DT + d];
        const int t = (p2.x < xv) + (p2.y < xv) + (p2.z < xv);
        const int j = 4 * q + t;
        const int b = 2 * j + (sXE[j * DT + d] < xv) + (p1.w < xv);

        const int rec = b * DT + d;
        const float4 rA = sRA[rec];   // {t0, inv_dx, a2, a1}
        const float4 rB = sRB[rec];   // {a0, c, s, e1}

        // --- Horner rational-quadratic evaluation ---
        const float xi   = fmaf(xv, rA.y, rA.x);
        const float P    = fmaf(fmaf(rA.z, xi, rA.w), xi, rB.x);
        const float den  = fmaf(fmaf(-rB.y, xi, rB.y), xi, rB.z);  // > 0 always
        const float rden = __fdividef(1.0f, den);
        const float yv   = P * rden;
        const float dl   = fmaf(-0.5f, rB.w, rB.z);                // dl = s - e1/2
        const float num  = fmaf(fmaf(rB.y, xi, rB.w), xi, dl);
        const float rs   = rB.z * rden;                            // s / den
        const float larg = rs * rs * num;                          // s^2 num / den^2

        yout[off]  = yv;
        ldout[off] = __logf(larg);
    }
}

extern "C" void kernel_launch(void* const* d_in, const int* in_sizes, int n_in,
                              void* d_out, int out_size) {
    const float* x      = (const float*)d_in[0];
    const float* params = (const float*)d_in[1];
    float* out = (float*)d_out;

    prep_kernel<<<(NDIM * 32 + 255) / 256, 256>>>(params);

    dim3 grid(NDIM / DT, BPT);    // 16 x 55 = 880 blocks ~= one full wave
    spline_kernel<<<grid, TPB>>>(x, out);
}

// round 13
// speedup vs baseline: 1.0503x; 1.0503x over previous
#include <cuda_runtime.h>
#include <math_constants.h>

#define NDIM  512
#define NKNOT 32
#define NDATA 65536
#define NBIN  (NKNOT + 1)     // 33: tail-low + 31 interior + tail-high

#define DT   32               // dims per block tile (one warp-width)
#define TPB  256              // 32 dims x 8 rows per iteration
#define RPB  256              // rows per block
#define TAILW 64.0f           // tail fake-bin width (power of 2 -> exact xi)

// Bin coefficient records, bin-major, natural dim order: g_RA/g_RB[b*NDIM + d]
//   RA = {t0 = -x_lo/dx, inv_dx, a2, a1}   (P = a2 xi^2 + a1 xi + a0)
//   RB = {a0, c, s, e1 = 2(s - dl)}        (den = -c xi^2 + c xi + s,
//                                           num =  c xi^2 + e1 xi + dl)
__device__ float4 g_RA[NBIN * NDIM];
__device__ float4 g_RB[NBIN * NDIM];
__device__ float4 g_P2[4 * NDIM];            // {xx[8q+1], xx[8q+3], xx[8q+5], 0}
__device__ float  g_XE[(NKNOT / 2) * NDIM];  // xx[2j]
__device__ float4 g_P1[NDIM];                // {xx7, xx15, xx23, xx31}

// ---------------------------------------------------------------------------
// Prep: one warp per dim. Inclusive shfl-scan builds xx/yy; lane k holds
// knot k. Bin b (1..31) emitted by lane b from (prev-lane, own) knots.
// ---------------------------------------------------------------------------
__device__ __forceinline__ void emit_rec(int b, int d, float x_lo, float dx,
                                         float y_lo, float dy, float dl, float dh) {
    const float inv_dx = 1.0f / dx;
    const float s = dy * inv_dx;
    const float c = dh + dl - 2.0f * s;
    g_RA[b * NDIM + d] = make_float4(-x_lo * inv_dx, inv_dx,
                                     -y_lo * c + dy * (s - dl),
                                     y_lo * c + dy * dl);
    g_RB[b * NDIM + d] = make_float4(y_lo * s, c, s, 2.0f * (s - dl));
}

__global__ void prep_kernel(const float* __restrict__ params) {
    const unsigned FULL = 0xFFFFFFFFu;
    const int d    = (blockIdx.x * blockDim.x + threadIdx.x) >> 5;  // dim = warp
    const int lane = threadIdx.x & 31;
    if (d >= NDIM) return;

    float edx = 0.0f, edy = 0.0f;
    if (lane >= 1) {
        edx = expf(params[2 * NDIM + d * (NKNOT - 1) + lane - 1]);
        edy = expf(params[2 * NDIM + NDIM * (NKNOT - 1) + d * (NKNOT - 1) + lane - 1]);
    }
    const float dd = expf(params[2 * NDIM + 2 * NDIM * (NKNOT - 1) + d * NKNOT + lane]);

    #pragma unroll
    for (int o = 1; o < 32; o <<= 1) {
        const float tx = __shfl_up_sync(FULL, edx, o);
        const float ty = __shfl_up_sync(FULL, edy, o);
        if (lane >= o) { edx += tx; edy += ty; }
    }
    const float xx = params[d] + edx;         // lane k holds xx[k]
    const float yy = params[NDIM + d] + edy;  // lane k holds yy[k]

    const float xxp = __shfl_up_sync(FULL, xx, 1);
    const float yyp = __shfl_up_sync(FULL, yy, 1);
    const float ddp = __shfl_up_sync(FULL, dd, 1);

    if (lane == 0)
        emit_rec(0, d, xx - TAILW, TAILW, yy - TAILW * dd, TAILW * dd, dd, dd);
    else
        emit_rec(lane, d, xxp, xx - xxp, yyp, yy - yyp, ddp, dd);
    if (lane == NKNOT - 1)
        emit_rec(NKNOT, d, xx, TAILW, yy, TAILW * dd, dd, dd);

    // P2 pivots (lanes 0..3 write quadrant q = lane)
    const int q = lane & 3;
    const float x1 = __shfl_sync(FULL, xx, 8 * q + 1);
    const float x3 = __shfl_sync(FULL, xx, 8 * q + 3);
    const float x5 = __shfl_sync(FULL, xx, 8 * q + 5);
    if (lane < 4)
        g_P2[lane * NDIM + d] = make_float4(x1, x3, x5, 0.0f);

    // Even-knot table (lanes 0..15 write j = lane)
    const float xe = __shfl_sync(FULL, xx, 2 * (lane & 15));
    if (lane < 16)
        g_XE[lane * NDIM + d] = xe;

    // L1 pivots
    const float p7  = __shfl_sync(FULL, xx, 7);
    const float p15 = __shfl_sync(FULL, xx, 15);
    const float p23 = __shfl_sync(FULL, xx, 23);
    const float p31 = __shfl_sync(FULL, xx, 31);
    if (lane == 0)
        g_P1[d] = make_float4(p7, p15, p23, p31);
}

// ---------------------------------------------------------------------------
// Main kernel (R11 shape, unroll 8): 32-dim tile, 256-row slab. Branchless
// bin search in [0,32]; unified Horner rational-quadratic evaluation.
// Gathers = 2x LDS.128, bank-conflict-free for any data-dependent bin.
// ---------------------------------------------------------------------------
__global__ __launch_bounds__(TPB, 5) void spline_kernel(
    const float* __restrict__ x, float* __restrict__ out)
{
    __shared__ float4 sRA[NBIN * DT];           // 16.5 KB
    __shared__ float4 sRB[NBIN * DT];           // 16.5 KB
    __shared__ float4 sP2[4 * DT];              // 2 KB
    __shared__ float  sXE[(NKNOT / 2) * DT];    // 2 KB

    const int dbase = blockIdx.x * DT;
    const int tid = threadIdx.x;

    #pragma unroll
    for (int i = tid; i < NBIN * DT; i += TPB) {
        int g = (i >> 5) * NDIM + dbase + (i & 31);
        sRA[i] = g_RA[g];
        sRB[i] = g_RB[g];
    }
    if (tid < 4 * DT)
        sP2[tid] = g_P2[(tid >> 5) * NDIM + dbase + (tid & 31)];
    #pragma unroll
    for (int i = tid; i < (NKNOT / 2) * DT; i += TPB)
        sXE[i] = g_XE[(i >> 5) * NDIM + dbase + (i & 31)];

    const int d  = tid & 31;
    const int rl = tid >> 5;                     // 0..7
    const int r0 = blockIdx.y * RPB;

    // Per-thread L1 pivots (hoisted; p1.w = xx[31]).
    const float4 p1 = g_P1[dbase + d];

    __syncthreads();

    float* __restrict__ yout  = out;
    float* __restrict__ ldout = out + NDATA * NDIM;

    unsigned off = (unsigned)(r0 + rl) * NDIM + dbase + d;
    const unsigned step = (TPB / DT) * NDIM;

    #pragma unroll 8
    for (int rr = rl; rr < RPB; rr += TPB / DT, off += step) {
        const float xv = __ldg(x + off);

        // --- tournament: b = #{knots < xv} in [0, 32] ---
        const int q = (p1.x < xv) + (p1.y < xv) + (p1.z < xv);
        const float4 p2 = sP2[q * DT + d];
        const int t = (p2.x < xv) + (p2.y < xv) + (p2.z < xv);
        const int j = 4 * q + t;
        const int b = 2 * j + (sXE[j * DT + d] < xv) + (p1.w < xv);

        const int rec = b * DT + d;
        const float4 rA = sRA[rec];   // {t0, inv_dx, a2, a1}
        const float4 rB = sRB[rec];   // {a0, c, s, e1}

        // --- Horner rational-quadratic evaluation ---
        const float xi   = fmaf(xv, rA.y, rA.x);
        const float P    = fmaf(fmaf(rA.z, xi, rA.w), xi, rB.x);
        const float den  = fmaf(fmaf(-rB.y, xi, rB.y), xi, rB.z);  // > 0 always
        const float rden = __fdividef(1.0f, den);
        const float yv   = P * rden;
        const float dl   = fmaf(-0.5f, rB.w, rB.z);                // dl = s - e1/2
        const float num  = fmaf(fmaf(rB.y, xi, rB.w), xi, dl);
        const float rs   = rB.z * rden;                            // s / den
        const float larg = rs * rs * num;                          // s^2 num / den^2

        yout[off]  = yv;
        ldout[off] = __logf(larg);
    }
}

extern "C" void kernel_launch(void* const* d_in, const int* in_sizes, int n_in,
                              void* d_out, int out_size) {
    const float* x      = (const float*)d_in[0];
    const float* params = (const float*)d_in[1];
    float* out = (float*)d_out;

    prep_kernel<<<(NDIM * 32 + 255) / 256, 256>>>(params);

    dim3 grid(NDIM / DT, NDATA / RPB);
    spline_kernel<<<grid, TPB>>>(x, out);
}

// round 14
// speedup vs baseline: 1.0535x; 1.0031x over previous
#include <cuda_runtime.h>
#include <math_constants.h>

#define NDIM  512
#define NKNOT 32
#define NDATA 65536
#define NBIN  (NKNOT + 1)     // 33: tail-low + 31 interior + tail-high

#define DT   32               // dims per block tile (one warp-width)
#define TPB  256              // 32 dims x 8 rows per iteration
#define RPB  256              // rows per block
#define TAILW 64.0f           // tail fake-bin width (power of 2 -> exact xi)

// Normalized bin records (P,Q divided by s so Q has leading coeff 1):
//   RA = {t0 = -x_lo/dx, inv_dx, a2', a1'}   (P' = a2' xi^2 + a1' xi + a0')
//   RB = {a0', c'}                            (Q' = 1 + c' xi (1-xi))
// y  = P'/Q';  y'(x) = (dP' - y dQ') / Q' * inv_dx  (== s^2 num/den^2)
__device__ float4 g_RA[NBIN * NDIM];
__device__ float2 g_RB[NBIN * NDIM];
__device__ float4 g_P2[4 * NDIM];            // {xx[8q+1], xx[8q+3], xx[8q+5], 0}
__device__ float  g_XE[(NKNOT / 2) * NDIM];  // xx[2j]
__device__ float4 g_P1[NDIM];                // {xx7, xx15, xx23, xx31}

// ---------------------------------------------------------------------------
// Prep: one warp per dim. Inclusive shfl-scan builds xx/yy; lane k holds
// knot k. Bin b (1..31) emitted by lane b from (prev-lane, own) knots.
// ---------------------------------------------------------------------------
__device__ __forceinline__ void emit_rec(int b, int d, float x_lo, float dx,
                                         float y_lo, float dy, float dl, float dh) {
    const float inv_dx = 1.0f / dx;
    const float s  = dy * inv_dx;
    const float rs = 1.0f / s;
    const float c  = dh + dl - 2.0f * s;
    const float cp = c * rs;
    g_RA[b * NDIM + d] = make_float4(-x_lo * inv_dx, inv_dx,
                                     (-y_lo * c + dy * (s - dl)) * rs,
                                     (y_lo * c + dy * dl) * rs);
    g_RB[b * NDIM + d] = make_float2(y_lo, cp);
}

__global__ void prep_kernel(const float* __restrict__ params) {
    const unsigned FULL = 0xFFFFFFFFu;
    const int d    = (blockIdx.x * blockDim.x + threadIdx.x) >> 5;  // dim = warp
    const int lane = threadIdx.x & 31;
    if (d >= NDIM) return;

    float edx = 0.0f, edy = 0.0f;
    if (lane >= 1) {
        edx = expf(params[2 * NDIM + d * (NKNOT - 1) + lane - 1]);
        edy = expf(params[2 * NDIM + NDIM * (NKNOT - 1) + d * (NKNOT - 1) + lane - 1]);
    }
    const float dd = expf(params[2 * NDIM + 2 * NDIM * (NKNOT - 1) + d * NKNOT + lane]);

    #pragma unroll
    for (int o = 1; o < 32; o <<= 1) {
        const float tx = __shfl_up_sync(FULL, edx, o);
        const float ty = __shfl_up_sync(FULL, edy, o);
        if (lane >= o) { edx += tx; edy += ty; }
    }
    const float xx = params[d] + edx;         // lane k holds xx[k]
    const float yy = params[NDIM + d] + edy;  // lane k holds yy[k]

    const float xxp = __shfl_up_sync(FULL, xx, 1);
    const float yyp = __shfl_up_sync(FULL, yy, 1);
    const float ddp = __shfl_up_sync(FULL, dd, 1);

    if (lane == 0)
        emit_rec(0, d, xx - TAILW, TAILW, yy - TAILW * dd, TAILW * dd, dd, dd);
    else
        emit_rec(lane, d, xxp, xx - xxp, yyp, yy - yyp, ddp, dd);
    if (lane == NKNOT - 1)
        emit_rec(NKNOT, d, xx, TAILW, yy, TAILW * dd, dd, dd);

    // P2 pivots (lanes 0..3 write quadrant q = lane)
    const int q = lane & 3;
    const float x1 = __shfl_sync(FULL, xx, 8 * q + 1);
    const float x3 = __shfl_sync(FULL, xx, 8 * q + 3);
    const float x5 = __shfl_sync(FULL, xx, 8 * q + 5);
    if (lane < 4)
        g_P2[lane * NDIM + d] = make_float4(x1, x3, x5, 0.0f);

    // Even-knot table (lanes 0..15 write j = lane)
    const float xe = __shfl_sync(FULL, xx, 2 * (lane & 15));
    if (lane < 16)
        g_XE[lane * NDIM + d] = xe;

    // L1 pivots
    const float p7  = __shfl_sync(FULL, xx, 7);
    const float p15 = __shfl_sync(FULL, xx, 15);
    const float p23 = __shfl_sync(FULL, xx, 23);
    const float p31 = __shfl_sync(FULL, xx, 31);
    if (lane == 0)
        g_P1[d] = make_float4(p7, p15, p23, p31);
}

// ---------------------------------------------------------------------------
// Main kernel: 32-dim tile, 256-row slab, unroll 8. Branchless bin search in
// [0,32]; normalized Horner RQ evaluation with quotient-rule log-derivative.
// Gathers = LDS.128 + LDS.64, bank-conflict-free for any data-dependent bin.
// ---------------------------------------------------------------------------
__global__ __launch_bounds__(TPB, 5) void spline_kernel(
    const float* __restrict__ x, float* __restrict__ out)
{
    __shared__ float4 sRA[NBIN * DT];           // 16.5 KB
    __shared__ float2 sRB[NBIN * DT];           // 8.25 KB
    __shared__ float4 sP2[4 * DT];              // 2 KB
    __shared__ float  sXE[(NKNOT / 2) * DT];    // 2 KB

    const int dbase = blockIdx.x * DT;
    const int tid = threadIdx.x;

    #pragma unroll
    for (int i = tid; i < NBIN * DT; i += TPB) {
        int g = (i >> 5) * NDIM + dbase + (i & 31);
        sRA[i] = g_RA[g];
        sRB[i] = g_RB[g];
    }
    if (tid < 4 * DT)
        sP2[tid] = g_P2[(tid >> 5) * NDIM + dbase + (tid & 31)];
    #pragma unroll
    for (int i = tid; i < (NKNOT / 2) * DT; i += TPB)
        sXE[i] = g_XE[(i >> 5) * NDIM + dbase + (i & 31)];

    const int d  = tid & 31;
    const int rl = tid >> 5;                     // 0..7
    const int r0 = blockIdx.y * RPB;

    // Per-thread L1 pivots (hoisted; p1.w = xx[31]).
    const float4 p1 = g_P1[dbase + d];

    __syncthreads();

    float* __restrict__ yout  = out;
    float* __restrict__ ldout = out + NDATA * NDIM;

    unsigned off = (unsigned)(r0 + rl) * NDIM + dbase + d;
    const unsigned step = (TPB / DT) * NDIM;

    #pragma unroll 8
    for (int rr = rl; rr < RPB; rr += TPB / DT, off += step) {
        const float xv = __ldg(x + off);

        // --- tournament: b = #{knots < xv} in [0, 32] ---
        const int q = (p1.x < xv) + (p1.y < xv) + (p1.z < xv);
        const float4 p2 = sP2[q * DT + d];
        const int t = (p2.x < xv) + (p2.y < xv) + (p2.z < xv);
        const int j = 4 * q + t;
        const int b = 2 * j + (sXE[j * DT + d] < xv) + (p1.w < xv);

        const int rec = b * DT + d;
        const float4 rA = sRA[rec];   // {t0, inv_dx, a2', a1'}
        const float2 rB = sRB[rec];   // {a0', c'}

        // --- normalized Horner RQ evaluation ---
        const float xi   = fmaf(xv, rA.y, rA.x);
        const float Pv   = fmaf(fmaf(rA.z, xi, rA.w), xi, rB.x);
        const float den  = fmaf(fmaf(-rB.y, xi, rB.y), xi, 1.0f);   // > 0 always
        const float rden = __fdividef(1.0f, den);
        const float yv   = Pv * rden;
        // y'(x) = (dP' - y*dQ') / Q' * inv_dx
        const float dP   = fmaf(rA.z + rA.z, xi, rA.w);             // 2a2' xi + a1'
        const float dQ   = fmaf(-(rB.y + rB.y), xi, rB.y);          // c'(1 - 2xi)
        const float tq   = fmaf(-yv, dQ, dP);
        const float larg = tq * rden * rA.y;

        yout[off]  = yv;
        ldout[off] = __logf(larg);
    }
}

extern "C" void kernel_launch(void* const* d_in, const int* in_sizes, int n_in,
                              void* d_out, int out_size) {
    const float* x      = (const float*)d_in[0];
    const float* params = (const float*)d_in[1];
    float* out = (float*)d_out;

    prep_kernel<<<(NDIM * 32 + 255) / 256, 256>>>(params);

    dim3 grid(NDIM / DT, NDATA / RPB);
    spline_kernel<<<grid, TPB>>>(x, out);
}